// round 1
// baseline (speedup 1.0000x reference)
#include <cuda_runtime.h>
#include <math.h>

#define BB   16
#define CH   32
#define HH   256
#define WW   256
#define NK   256
#define PLANE (HH*WW)              // 65536
#define NPIX  (BB*HH*WW)           // 1048576
#define NSTEPS 5

// Scratch (allocation-free: device globals)
__device__ float g_state[BB*CH*PLANE];
__device__ float g_hidden[BB*CH*PLANE];

// ---------------------------------------------------------------------------
// Stem: conv3x3 (1 -> 32), pad 1, + ReLU.  One thread per pixel, 32 couts.
// ---------------------------------------------------------------------------
__global__ __launch_bounds__(256) void stem_kernel(
    const float* __restrict__ x, const float* __restrict__ w,
    const float* __restrict__ bias)
{
    __shared__ float sw[CH*9];
    __shared__ float sb[CH];
    if (threadIdx.x < CH*9) sw[threadIdx.x] = w[threadIdx.x];
    if (threadIdx.x < CH)   sb[threadIdx.x] = bias[threadIdx.x];
    __syncthreads();

    int p  = blockIdx.x * 256 + threadIdx.x;
    int xx = p & (WW-1);
    int yy = (p >> 8) & (HH-1);
    int b  = p >> 16;

    float v[9];
#pragma unroll
    for (int ky = 0; ky < 3; ky++)
#pragma unroll
        for (int kx = 0; kx < 3; kx++) {
            int iy = yy + ky - 1, ix = xx + kx - 1;
            v[ky*3+kx] = (iy >= 0 && iy < HH && ix >= 0 && ix < WW)
                         ? x[b*PLANE + iy*WW + ix] : 0.f;
        }

    float* ob = g_state + (size_t)b*CH*PLANE + yy*WW + xx;
#pragma unroll
    for (int co = 0; co < CH; co++) {
        float a = sb[co];
#pragma unroll
        for (int t = 0; t < 9; t++) a = fmaf(sw[co*9+t], v[t], a);
        ob[co*PLANE] = fmaxf(a, 0.f);
    }
}

// ---------------------------------------------------------------------------
// conv3x3 (32 -> 32), pad 1, + ReLU.   state -> hidden
// Weights rearranged in smem as [tap][co][ci] so the ci axis is float4-loadable.
// ---------------------------------------------------------------------------
__global__ __launch_bounds__(256) void conv3x3_relu_kernel(
    const float* __restrict__ w, const float* __restrict__ bias)
{
    __shared__ float4 sw[9*CH*CH/4];   // 9216 floats = 36 KB
    __shared__ float  sb[CH];
    float* swf = (float*)sw;
    for (int i = threadIdx.x; i < 9*CH*CH; i += 256) {
        int tap = i >> 10;             // /1024
        int r   = i & 1023;
        int co  = r >> 5;
        int ci  = r & 31;
        swf[i] = w[(co*CH + ci)*9 + tap];
    }
    if (threadIdx.x < CH) sb[threadIdx.x] = bias[threadIdx.x];
    __syncthreads();

    int p  = blockIdx.x * 256 + threadIdx.x;
    int xx = p & (WW-1);
    int yy = (p >> 8) & (HH-1);
    int b  = p >> 16;
    const float* inb = g_state + (size_t)b*CH*PLANE;

    float acc[CH];
#pragma unroll
    for (int co = 0; co < CH; co++) acc[co] = sb[co];

    for (int ky = 0; ky < 3; ky++) {
        int iy = yy + ky - 1;
        if (iy < 0 || iy >= HH) continue;
        for (int kx = 0; kx < 3; kx++) {
            int ix = xx + kx - 1;
            if (ix < 0 || ix >= WW) continue;
            int tap = ky*3 + kx;
            float v[CH];
            const float* ip = inb + iy*WW + ix;
#pragma unroll
            for (int ci = 0; ci < CH; ci++) v[ci] = ip[ci*PLANE];
            const float4* wt = sw + tap*(CH*CH/4);
#pragma unroll
            for (int co = 0; co < CH; co++) {
                float a = acc[co];
#pragma unroll
                for (int q = 0; q < CH/4; q++) {
                    float4 wv = wt[co*(CH/4) + q];
                    a = fmaf(wv.x, v[q*4+0], a);
                    a = fmaf(wv.y, v[q*4+1], a);
                    a = fmaf(wv.z, v[q*4+2], a);
                    a = fmaf(wv.w, v[q*4+3], a);
                }
                acc[co] = a;
            }
        }
    }

    float* ob = g_hidden + (size_t)b*CH*PLANE + yy*WW + xx;
#pragma unroll
    for (int co = 0; co < CH; co++) ob[co*PLANE] = fmaxf(acc[co], 0.f);
}

// ---------------------------------------------------------------------------
// Fused: delta = up2 @ hidden + b ; beta = sigmoid(tau @ state + b);
//        z = beta*state + (1-beta)*delta ; state = codebook[argmin ||z-c||^2]
// Purely per-pixel => state updated in place.
// ---------------------------------------------------------------------------
__global__ __launch_bounds__(256) void fuse_vq_kernel(
    const float* __restrict__ up2w, const float* __restrict__ up2b,
    const float* __restrict__ tauw, const float* __restrict__ taub,
    const float* __restrict__ cb)
{
    __shared__ float4 s_up2[CH*CH/4];
    __shared__ float4 s_tau[CH*CH/4];
    __shared__ float4 s_cb[NK*CH/4];   // 8192 floats = 32 KB
    __shared__ float  s_cn[NK];
    __shared__ float  s_up2b[CH], s_taub[CH];

    for (int i = threadIdx.x; i < CH*CH; i += 256) {
        ((float*)s_up2)[i] = up2w[i];
        ((float*)s_tau)[i] = tauw[i];
    }
    for (int i = threadIdx.x; i < NK*CH; i += 256) ((float*)s_cb)[i] = cb[i];
    if (threadIdx.x < CH) {
        s_up2b[threadIdx.x] = up2b[threadIdx.x];
        s_taub[threadIdx.x] = taub[threadIdx.x];
    }
    __syncthreads();
    {   // ||c||^2 per code (blockDim == NK == 256)
        int k = threadIdx.x;
        float s = 0.f;
#pragma unroll
        for (int q = 0; q < CH/4; q++) {
            float4 c4 = s_cb[k*(CH/4) + q];
            s += c4.x*c4.x + c4.y*c4.y + c4.z*c4.z + c4.w*c4.w;
        }
        s_cn[k] = s;
    }
    __syncthreads();

    int p   = blockIdx.x * 256 + threadIdx.x;
    int b   = p >> 16;
    int off = p & (PLANE-1);
    float*       sp = g_state  + (size_t)b*CH*PLANE + off;
    const float* hp = g_hidden + (size_t)b*CH*PLANE + off;

    float s[CH], h[CH];
#pragma unroll
    for (int c = 0; c < CH; c++) { s[c] = sp[c*PLANE]; h[c] = hp[c*PLANE]; }

    // delta = up2 @ h + b   (h dead afterwards)
    float dl[CH];
#pragma unroll
    for (int co = 0; co < CH; co++) {
        float d = s_up2b[co];
#pragma unroll
        for (int q = 0; q < CH/4; q++) {
            float4 wv = s_up2[co*(CH/4) + q];
            d = fmaf(wv.x, h[q*4+0], d);
            d = fmaf(wv.y, h[q*4+1], d);
            d = fmaf(wv.z, h[q*4+2], d);
            d = fmaf(wv.w, h[q*4+3], d);
        }
        dl[co] = d;
    }
    // beta & mix (overwrite dl with z)
#pragma unroll
    for (int co = 0; co < CH; co++) {
        float t = s_taub[co];
#pragma unroll
        for (int q = 0; q < CH/4; q++) {
            float4 wv = s_tau[co*(CH/4) + q];
            t = fmaf(wv.x, s[q*4+0], t);
            t = fmaf(wv.y, s[q*4+1], t);
            t = fmaf(wv.z, s[q*4+2], t);
            t = fmaf(wv.w, s[q*4+3], t);
        }
        float beta = 1.f / (1.f + expf(-t));
        dl[co] = beta * s[co] + (1.f - beta) * dl[co];
    }
    // VQ: argmin_k ||c_k||^2 - 2 z.c_k  (first-min on ties, like argmin)
    float bestd = 3.4e38f;
    int   bestk = 0;
    for (int k = 0; k < NK; k++) {
        float dot = 0.f;
#pragma unroll
        for (int q = 0; q < CH/4; q++) {
            float4 c4 = s_cb[k*(CH/4) + q];
            dot = fmaf(c4.x, dl[q*4+0], dot);
            dot = fmaf(c4.y, dl[q*4+1], dot);
            dot = fmaf(c4.z, dl[q*4+2], dot);
            dot = fmaf(c4.w, dl[q*4+3], dot);
        }
        float d = fmaf(-2.f, dot, s_cn[k]);
        if (d < bestd) { bestd = d; bestk = k; }
    }
#pragma unroll
    for (int q = 0; q < CH/4; q++) {
        float4 c4 = s_cb[bestk*(CH/4) + q];
        sp[(q*4+0)*PLANE] = c4.x;
        sp[(q*4+1)*PLANE] = c4.y;
        sp[(q*4+2)*PLANE] = c4.z;
        sp[(q*4+3)*PLANE] = c4.w;
    }
}

// ---------------------------------------------------------------------------
// Decoder: 1x1 conv (32 -> 1) + sigmoid
// ---------------------------------------------------------------------------
__global__ __launch_bounds__(256) void dec_kernel(
    const float* __restrict__ w, const float* __restrict__ bias,
    float* __restrict__ out)
{
    __shared__ float sw[CH];
    __shared__ float sb;
    if (threadIdx.x < CH) sw[threadIdx.x] = w[threadIdx.x];
    if (threadIdx.x == 0) sb = bias[0];
    __syncthreads();

    int p   = blockIdx.x * 256 + threadIdx.x;
    int b   = p >> 16;
    int off = p & (PLANE-1);
    const float* sp = g_state + (size_t)b*CH*PLANE + off;
    float a = sb;
#pragma unroll
    for (int c = 0; c < CH; c++) a = fmaf(sw[c], sp[c*PLANE], a);
    out[p] = 1.f / (1.f + expf(-a));
}

// ---------------------------------------------------------------------------
extern "C" void kernel_launch(void* const* d_in, const int* in_sizes, int n_in,
                              void* d_out, int out_size)
{
    const float* x      = (const float*)d_in[0];
    const float* stem_w = (const float*)d_in[1];
    const float* stem_b = (const float*)d_in[2];
    const float* up1_w  = (const float*)d_in[3];
    const float* up1_b  = (const float*)d_in[4];
    const float* up2_w  = (const float*)d_in[5];
    const float* up2_b  = (const float*)d_in[6];
    const float* tau_w  = (const float*)d_in[7];
    const float* tau_b  = (const float*)d_in[8];
    const float* cbk    = (const float*)d_in[9];
    const float* dec_w  = (const float*)d_in[10];
    const float* dec_b  = (const float*)d_in[11];
    // d_in[12] = n_steps (fixed at 5 by the problem setup; loop must be host-static)

    dim3 grid(NPIX / 256), blk(256);

    stem_kernel<<<grid, blk>>>(x, stem_w, stem_b);
    for (int t = 0; t < NSTEPS; t++) {
        conv3x3_relu_kernel<<<grid, blk>>>(up1_w, up1_b);
        fuse_vq_kernel<<<grid, blk>>>(up2_w, up2_b, tau_w, tau_b, cbk);
    }
    dec_kernel<<<grid, blk>>>(dec_w, dec_b, (float*)d_out);
}

// round 2
// speedup vs baseline: 1.7373x; 1.7373x over previous
#include <cuda_runtime.h>
#include <math.h>

typedef unsigned long long u64;
typedef unsigned char u8;

#define BB   16
#define CH   32
#define HH   256
#define WW   256
#define NK   256
#define PLANE 65536
#define NPIX  1048576
#define NSTEPS 5

// ---------------- device scratch (allocation-free) ----------------
__device__ float  g_state [BB*CH*PLANE];
__device__ float  g_hidden[BB*CH*PLANE];
__device__ u8     g_idxA[NPIX];
__device__ u8     g_idxB[NPIX];
__device__ float4 g_convlut[9*NK*CH/4];   // T[tap][k][co], co contiguous (128B rows)
__device__ float4 g_Alut[NK*CH/4];        // beta_k * c_k
__device__ float4 g_Blut[NK*CH/4];        // 1 - beta_k
__device__ float  g_declut[NK];           // sigmoid(dec . c_k + b)

// ---------------- packed f32x2 helpers ----------------
__device__ __forceinline__ u64 pk(float a, float b){
    u64 r; asm("mov.b64 %0,{%1,%2};" : "=l"(r) : "f"(a), "f"(b)); return r;
}
__device__ __forceinline__ void upk(u64 v, float& a, float& b){
    asm("mov.b64 {%0,%1},%2;" : "=f"(a), "=f"(b) : "l"(v));
}
__device__ __forceinline__ u64 fma2(u64 a, u64 b, u64 c){
    u64 d; asm("fma.rn.f32x2 %0,%1,%2,%3;" : "=l"(d) : "l"(a), "l"(b), "l"(c)); return d;
}
__device__ __forceinline__ u64 mul2(u64 a, u64 b){
    u64 d; asm("mul.rn.f32x2 %0,%1,%2;" : "=l"(d) : "l"(a), "l"(b)); return d;
}
__device__ __forceinline__ u64 add2(u64 a, u64 b){
    u64 d; asm("add.rn.f32x2 %0,%1,%2;" : "=l"(d) : "l"(a), "l"(b)); return d;
}

// VQ argmin over 256 codes; z2 = 16 channel-pairs; cb2 = codebook rows as ulonglong2
__device__ __forceinline__ int vq_argmin(const u64* z2, const ulonglong2* cb2,
                                         const float* cn)
{
    float bestd = 3.4e38f;
    int   bestk = 0;
#pragma unroll 4
    for (int k = 0; k < NK; k++) {
        const ulonglong2* r = cb2 + k*8;
        ulonglong2 c = r[0];
        u64 acc = mul2(c.x, z2[0]);
        acc = fma2(c.y, z2[1], acc);
#pragma unroll
        for (int j = 1; j < 8; j++) {
            c = r[j];
            acc = fma2(c.x, z2[2*j],   acc);
            acc = fma2(c.y, z2[2*j+1], acc);
        }
        float a, b; upk(acc, a, b);
        float d = fmaf(-2.f, a + b, cn[k]);
        if (d < bestd) { bestd = d; bestk = k; }
    }
    return bestk;
}

// ---------------- LUT builders (tiny) ----------------
__global__ void build_conv_lut(const float* __restrict__ w, const float* __restrict__ cb)
{
    int t = blockIdx.x * 256 + threadIdx.x;           // 9*256*32 = 73728
    if (t >= 9*NK*CH) return;
    int co  = t & 31;
    int k   = (t >> 5) & 255;
    int tap = t >> 13;
    float s = 0.f;
#pragma unroll
    for (int ci = 0; ci < CH; ci++)
        s = fmaf(w[(co*CH + ci)*9 + tap], cb[k*CH + ci], s);
    ((float*)g_convlut)[(tap*NK + k)*CH + co] = s;
}

__global__ void build_mix_lut(const float* __restrict__ tw, const float* __restrict__ tb,
                              const float* __restrict__ cb)
{
    int t = blockIdx.x * 256 + threadIdx.x;           // 8192
    if (t >= NK*CH) return;
    int co = t & 31, k = t >> 5;
    float s = tb[co];
#pragma unroll
    for (int ci = 0; ci < CH; ci++)
        s = fmaf(tw[co*CH + ci], cb[k*CH + ci], s);
    float beta = 1.f / (1.f + expf(-s));
    ((float*)g_Alut)[k*CH + co] = beta * cb[k*CH + co];
    ((float*)g_Blut)[k*CH + co] = 1.f - beta;
}

__global__ void build_dec_lut(const float* __restrict__ dw, const float* __restrict__ db,
                              const float* __restrict__ cb)
{
    int k = threadIdx.x;                              // 256
    float s = db[0];
#pragma unroll
    for (int ci = 0; ci < CH; ci++)
        s = fmaf(dw[ci], cb[k*CH + ci], s);
    g_declut[k] = 1.f / (1.f + expf(-s));
}

// ---------------- stem: conv3x3 (1->32) + relu ----------------
__global__ __launch_bounds__(256) void stem_kernel(
    const float* __restrict__ x, const float* __restrict__ w,
    const float* __restrict__ bias)
{
    __shared__ float sw[CH*9];
    __shared__ float sb[CH];
    if (threadIdx.x < CH*9) sw[threadIdx.x] = w[threadIdx.x];
    if (threadIdx.x < CH)   sb[threadIdx.x] = bias[threadIdx.x];
    __syncthreads();

    int p  = blockIdx.x * 256 + threadIdx.x;
    int xx = p & (WW-1);
    int yy = (p >> 8) & (HH-1);
    int b  = p >> 16;

    float v[9];
#pragma unroll
    for (int ky = 0; ky < 3; ky++)
#pragma unroll
        for (int kx = 0; kx < 3; kx++) {
            int iy = yy + ky - 1, ix = xx + kx - 1;
            v[ky*3+kx] = (iy >= 0 && iy < HH && ix >= 0 && ix < WW)
                         ? x[b*PLANE + iy*WW + ix] : 0.f;
        }

    float* ob = g_state + (size_t)b*CH*PLANE + yy*WW + xx;
#pragma unroll
    for (int co = 0; co < CH; co++) {
        float a = sb[co];
#pragma unroll
        for (int t = 0; t < 9; t++) a = fmaf(sw[co*9+t], v[t], a);
        ob[co*PLANE] = fmaxf(a, 0.f);
    }
}

// ---------------- dense conv3x3 (32->32)+relu, state->hidden (step 0 only) ----------------
__global__ __launch_bounds__(256) void conv3x3_relu_kernel(
    const float* __restrict__ w, const float* __restrict__ bias)
{
    __shared__ float4 sw4[9*CH*CH/4];   // [tap][co][ci]
    __shared__ float  sb[CH];
    float* swf = (float*)sw4;
    for (int i = threadIdx.x; i < 9*CH*CH; i += 256) {
        int tap = i >> 10;
        int r   = i & 1023;
        int co  = r >> 5;
        int ci  = r & 31;
        swf[i] = w[(co*CH + ci)*9 + tap];
    }
    if (threadIdx.x < CH) sb[threadIdx.x] = bias[threadIdx.x];
    __syncthreads();

    int p  = blockIdx.x * 256 + threadIdx.x;
    int xx = p & (WW-1);
    int yy = (p >> 8) & (HH-1);
    int b  = p >> 16;
    const float* inb = g_state + (size_t)b*CH*PLANE;

    u64 acc2[CH];
#pragma unroll
    for (int co = 0; co < CH; co++) acc2[co] = 0ull;

    for (int ky = 0; ky < 3; ky++) {
        int iy = yy + ky - 1;
        if (iy < 0 || iy >= HH) continue;
        for (int kx = 0; kx < 3; kx++) {
            int ix = xx + kx - 1;
            if (ix < 0 || ix >= WW) continue;
            int tap = ky*3 + kx;
            const float* ip = inb + iy*WW + ix;
            u64 v2[CH/2];
#pragma unroll
            for (int q = 0; q < CH/2; q++)
                v2[q] = pk(ip[(2*q)*PLANE], ip[(2*q+1)*PLANE]);
            const ulonglong2* wt = (const ulonglong2*)(sw4 + tap*(CH*CH/4));
#pragma unroll
            for (int co = 0; co < CH; co++) {
                const ulonglong2* r = wt + co*8;
                u64 a = acc2[co];
#pragma unroll
                for (int j = 0; j < 8; j++) {
                    ulonglong2 c = r[j];
                    a = fma2(c.x, v2[2*j],   a);
                    a = fma2(c.y, v2[2*j+1], a);
                }
                acc2[co] = a;
            }
        }
    }

    float* ob = g_hidden + (size_t)b*CH*PLANE + yy*WW + xx;
#pragma unroll
    for (int co = 0; co < CH; co++) {
        float a, bq; upk(acc2[co], a, bq);
        ob[co*PLANE] = fmaxf(a + bq + sb[co], 0.f);
    }
}

// ---------------- dense fuse+VQ (step 0): state,hidden -> idxA ----------------
__global__ __launch_bounds__(256) void fuse_dense_kernel(
    const float* __restrict__ up2w, const float* __restrict__ up2b,
    const float* __restrict__ tauw, const float* __restrict__ taub,
    const float* __restrict__ cb)
{
    __shared__ float4 s_cb4[NK*CH/4];   // 32 KB
    __shared__ float  s_cn[NK];
    __shared__ float4 s_u[CH*CH/4];
    __shared__ float4 s_t[CH*CH/4];
    __shared__ float  s_ub[CH], s_tb[CH];

    for (int i = threadIdx.x; i < NK*CH; i += 256) ((float*)s_cb4)[i] = cb[i];
    for (int i = threadIdx.x; i < CH*CH; i += 256) {
        ((float*)s_u)[i] = up2w[i];
        ((float*)s_t)[i] = tauw[i];
    }
    if (threadIdx.x < CH) { s_ub[threadIdx.x] = up2b[threadIdx.x];
                            s_tb[threadIdx.x] = taub[threadIdx.x]; }
    __syncthreads();
    {
        int k = threadIdx.x;
        const float* cf = (const float*)s_cb4;
        float s = 0.f;
#pragma unroll
        for (int ci = 0; ci < CH; ci++) s = fmaf(cf[k*CH+ci], cf[k*CH+ci], s);
        s_cn[k] = s;
    }
    __syncthreads();

    int p   = blockIdx.x * 256 + threadIdx.x;
    int b   = p >> 16;
    int off = p & (PLANE-1);
    const float* sp = g_state  + (size_t)b*CH*PLANE + off;
    const float* hp = g_hidden + (size_t)b*CH*PLANE + off;

    // hidden -> packed pairs
    u64 h2[CH/2];
#pragma unroll
    for (int q = 0; q < CH/2; q++) h2[q] = pk(hp[(2*q)*PLANE], hp[(2*q+1)*PLANE]);

    // delta = up2 @ h + b
    float d[CH];
    const ulonglong2* uw = (const ulonglong2*)s_u;
#pragma unroll
    for (int co = 0; co < CH; co++) {
        const ulonglong2* r = uw + co*8;
        ulonglong2 c = r[0];
        u64 acc = mul2(c.x, h2[0]); acc = fma2(c.y, h2[1], acc);
#pragma unroll
        for (int j = 1; j < 8; j++) {
            c = r[j];
            acc = fma2(c.x, h2[2*j], acc); acc = fma2(c.y, h2[2*j+1], acc);
        }
        float a, bq; upk(acc, a, bq);
        d[co] = a + bq + s_ub[co];
    }

    // state
    float s[CH]; u64 s2[CH/2];
#pragma unroll
    for (int ci = 0; ci < CH; ci++) s[ci] = sp[ci*PLANE];
#pragma unroll
    for (int q = 0; q < CH/2; q++) s2[q] = pk(s[2*q], s[2*q+1]);

    // beta & mix (z overwrites d)
    const ulonglong2* tw = (const ulonglong2*)s_t;
#pragma unroll
    for (int co = 0; co < CH; co++) {
        const ulonglong2* r = tw + co*8;
        ulonglong2 c = r[0];
        u64 acc = mul2(c.x, s2[0]); acc = fma2(c.y, s2[1], acc);
#pragma unroll
        for (int j = 1; j < 8; j++) {
            c = r[j];
            acc = fma2(c.x, s2[2*j], acc); acc = fma2(c.y, s2[2*j+1], acc);
        }
        float a, bq; upk(acc, a, bq);
        float t = a + bq + s_tb[co];
        float beta = 1.f / (1.f + expf(-t));
        d[co] = beta * s[co] + (1.f - beta) * d[co];
    }

    u64 z2[CH/2];
#pragma unroll
    for (int q = 0; q < CH/2; q++) z2[q] = pk(d[2*q], d[2*q+1]);

    int k = vq_argmin(z2, (const ulonglong2*)s_cb4, s_cn);
    g_idxA[p] = (u8)k;
}

// ---------------- fast step (t>=1): idx -> idx  (conv-LUT + mix-LUT + VQ) ----------------
__global__ __launch_bounds__(256) void step_fast_kernel(
    const float* __restrict__ up1b, const float* __restrict__ up2w,
    const float* __restrict__ up2b, const float* __restrict__ cb, int dir)
{
    __shared__ float4 s_cb4[NK*CH/4];
    __shared__ float  s_cn[NK];
    __shared__ float4 s_u[CH*CH/4];
    __shared__ float  s_b1[CH], s_ub[CH];

    for (int i = threadIdx.x; i < NK*CH; i += 256) ((float*)s_cb4)[i] = cb[i];
    for (int i = threadIdx.x; i < CH*CH; i += 256) ((float*)s_u)[i] = up2w[i];
    if (threadIdx.x < CH) { s_b1[threadIdx.x] = up1b[threadIdx.x];
                            s_ub[threadIdx.x] = up2b[threadIdx.x]; }
    __syncthreads();
    {
        int k = threadIdx.x;
        const float* cf = (const float*)s_cb4;
        float s = 0.f;
#pragma unroll
        for (int ci = 0; ci < CH; ci++) s = fmaf(cf[k*CH+ci], cf[k*CH+ci], s);
        s_cn[k] = s;
    }
    __syncthreads();

    const u8* iin  = dir ? g_idxB : g_idxA;
    u8*       iout = dir ? g_idxA : g_idxB;

    int p  = blockIdx.x * 256 + threadIdx.x;
    int xx = p & (WW-1);
    int yy = (p >> 8) & (HH-1);
    const u8* ib = iin + (p & ~(PLANE-1));

    // hidden = relu(bias + sum_taps T[tap][idx_nbr])  (packed channel pairs)
    u64 h2[CH/2];
#pragma unroll
    for (int q = 0; q < CH/2; q++) h2[q] = 0ull;

    for (int ky = 0; ky < 3; ky++) {
        int iy = yy + ky - 1;
        if (iy < 0 || iy >= HH) continue;
        for (int kx = 0; kx < 3; kx++) {
            int ix = xx + kx - 1;
            if (ix < 0 || ix >= WW) continue;
            int id = ib[iy*WW + ix];
            const ulonglong2* row =
                (const ulonglong2*)(g_convlut + ((ky*3+kx)*NK + id)*(CH/4));
#pragma unroll
            for (int j = 0; j < 8; j++) {
                ulonglong2 c = row[j];
                h2[2*j]   = add2(h2[2*j],   c.x);
                h2[2*j+1] = add2(h2[2*j+1], c.y);
            }
        }
    }
#pragma unroll
    for (int q = 0; q < CH/2; q++) {
        float a, bq; upk(h2[q], a, bq);
        a  = fmaxf(a  + s_b1[2*q],   0.f);
        bq = fmaxf(bq + s_b1[2*q+1], 0.f);
        h2[q] = pk(a, bq);
    }

    // delta = up2 @ h + b
    float d[CH];
    const ulonglong2* uw = (const ulonglong2*)s_u;
#pragma unroll
    for (int co = 0; co < CH; co++) {
        const ulonglong2* r = uw + co*8;
        ulonglong2 c = r[0];
        u64 acc = mul2(c.x, h2[0]); acc = fma2(c.y, h2[1], acc);
#pragma unroll
        for (int j = 1; j < 8; j++) {
            c = r[j];
            acc = fma2(c.x, h2[2*j], acc); acc = fma2(c.y, h2[2*j+1], acc);
        }
        float a, bq; upk(acc, a, bq);
        d[co] = a + bq + s_ub[co];
    }

    // z = A[idx] + B[idx] * delta   (per-channel, packed)
    int id0 = iin[p];
    const ulonglong2* ar = (const ulonglong2*)(g_Alut + id0*(CH/4));
    const ulonglong2* br = (const ulonglong2*)(g_Blut + id0*(CH/4));
    u64 z2[CH/2];
#pragma unroll
    for (int j = 0; j < 8; j++) {
        ulonglong2 A = ar[j], Bv = br[j];
        z2[2*j]   = fma2(Bv.x, pk(d[4*j],   d[4*j+1]), A.x);
        z2[2*j+1] = fma2(Bv.y, pk(d[4*j+2], d[4*j+3]), A.y);
    }

    int k = vq_argmin(z2, (const ulonglong2*)s_cb4, s_cn);
    iout[p] = (u8)k;
}

// ---------------- decoder: pure LUT ----------------
__global__ __launch_bounds__(256) void dec_lut_kernel(float* __restrict__ out)
{
    __shared__ float s_d[NK];
    s_d[threadIdx.x] = g_declut[threadIdx.x];
    __syncthreads();
    int p = blockIdx.x * 256 + threadIdx.x;
    out[p] = s_d[g_idxA[p]];
}

// ---------------------------------------------------------------------------
extern "C" void kernel_launch(void* const* d_in, const int* in_sizes, int n_in,
                              void* d_out, int out_size)
{
    const float* x      = (const float*)d_in[0];
    const float* stem_w = (const float*)d_in[1];
    const float* stem_b = (const float*)d_in[2];
    const float* up1_w  = (const float*)d_in[3];
    const float* up1_b  = (const float*)d_in[4];
    const float* up2_w  = (const float*)d_in[5];
    const float* up2_b  = (const float*)d_in[6];
    const float* tau_w  = (const float*)d_in[7];
    const float* tau_b  = (const float*)d_in[8];
    const float* cbk    = (const float*)d_in[9];
    const float* dec_w  = (const float*)d_in[10];
    const float* dec_b  = (const float*)d_in[11];
    // d_in[12] = n_steps (fixed at 5; loop is host-static for graph capture)

    dim3 grid(NPIX / 256), blk(256);

    stem_kernel<<<grid, blk>>>(x, stem_w, stem_b);
    build_conv_lut<<<(9*NK*CH)/256, 256>>>(up1_w, cbk);
    build_mix_lut<<<(NK*CH)/256, 256>>>(tau_w, tau_b, cbk);
    build_dec_lut<<<1, 256>>>(dec_w, dec_b, cbk);

    // step 0: dense path -> idxA
    conv3x3_relu_kernel<<<grid, blk>>>(up1_w, up1_b);
    fuse_dense_kernel<<<grid, blk>>>(up2_w, up2_b, tau_w, tau_b, cbk);

    // steps 1..4: LUT path, ping-pong A<->B (ends in A)
    step_fast_kernel<<<grid, blk>>>(up1_b, up2_w, up2_b, cbk, 0); // A->B
    step_fast_kernel<<<grid, blk>>>(up1_b, up2_w, up2_b, cbk, 1); // B->A
    step_fast_kernel<<<grid, blk>>>(up1_b, up2_w, up2_b, cbk, 0); // A->B
    step_fast_kernel<<<grid, blk>>>(up1_b, up2_w, up2_b, cbk, 1); // B->A

    dec_lut_kernel<<<grid, blk>>>((float*)d_out);
}

// round 3
// speedup vs baseline: 1.7725x; 1.0203x over previous
#include <cuda_runtime.h>
#include <math.h>

typedef unsigned long long u64;
typedef unsigned char u8;

#define BB   16
#define CH   32
#define HH   256
#define WW   256
#define NK   256
#define PLANE 65536
#define NPIX  1048576

// ---------------- device scratch (allocation-free) ----------------
__device__ float  g_state [BB*CH*PLANE];
__device__ float  g_hidden[BB*CH*PLANE];
__device__ u8     g_idxA[NPIX];
__device__ u8     g_idxB[NPIX];
__device__ float4 g_convlut[9*NK*CH/4];   // T[tap][k][co] (+ up1_b folded into tap 4)
__device__ float4 g_Alut[NK*CH/4];        // beta_k * c_k
__device__ float4 g_Blut[NK*CH/4];        // 1 - beta_k
__device__ float  g_declut[NK];           // sigmoid(dec . c_k + b)

// ---------------- packed f32x2 helpers ----------------
__device__ __forceinline__ u64 pk(float a, float b){
    u64 r; asm("mov.b64 %0,{%1,%2};" : "=l"(r) : "f"(a), "f"(b)); return r;
}
__device__ __forceinline__ void upk(u64 v, float& a, float& b){
    asm("mov.b64 {%0,%1},%2;" : "=f"(a), "=f"(b) : "l"(v));
}
__device__ __forceinline__ u64 fma2(u64 a, u64 b, u64 c){
    u64 d; asm("fma.rn.f32x2 %0,%1,%2,%3;" : "=l"(d) : "l"(a), "l"(b), "l"(c)); return d;
}
__device__ __forceinline__ u64 mul2(u64 a, u64 b){
    u64 d; asm("mul.rn.f32x2 %0,%1,%2;" : "=l"(d) : "l"(a), "l"(b)); return d;
}
__device__ __forceinline__ u64 add2(u64 a, u64 b){
    u64 d; asm("add.rn.f32x2 %0,%1,%2;" : "=l"(d) : "l"(a), "l"(b)); return d;
}

// VQ argmin over 256 codes; z2 = 16 channel-pairs; cb2 = codebook rows (smem).
// Chain order identical to the R2-passing version.
__device__ __forceinline__ int vq_argmin(const u64* z2, const ulonglong2* cb2,
                                         const float* cn)
{
    float bestd = 3.4e38f;
    int   bestk = 0;
#pragma unroll 4
    for (int k = 0; k < NK; k++) {
        const ulonglong2* r = cb2 + k*8;
        ulonglong2 c = r[0];
        u64 acc = mul2(c.x, z2[0]);
        acc = fma2(c.y, z2[1], acc);
#pragma unroll
        for (int j = 1; j < 8; j++) {
            c = r[j];
            acc = fma2(c.x, z2[2*j],   acc);
            acc = fma2(c.y, z2[2*j+1], acc);
        }
        float a, b; upk(acc, a, b);
        float d = fmaf(-2.f, a + b, cn[k]);
        if (d < bestd) { bestd = d; bestk = k; }
    }
    return bestk;
}

// GEMV helper: one output channel: dot(row(8 x ulonglong2), v2[16]) -> scalar
__device__ __forceinline__ float gemv_row(const ulonglong2* r, const u64* v2)
{
    ulonglong2 c = r[0];
    u64 acc = mul2(c.x, v2[0]); acc = fma2(c.y, v2[1], acc);
#pragma unroll
    for (int j = 1; j < 8; j++) {
        c = r[j];
        acc = fma2(c.x, v2[2*j], acc); acc = fma2(c.y, v2[2*j+1], acc);
    }
    float a, b; upk(acc, a, b);
    return a + b;
}

// ---------------- merged LUT builder ----------------
__global__ void build_luts(const float* __restrict__ up1w, const float* __restrict__ up1b,
                           const float* __restrict__ tauw, const float* __restrict__ taub,
                           const float* __restrict__ decw, const float* __restrict__ decb,
                           const float* __restrict__ cb)
{
    int t = blockIdx.x * 256 + threadIdx.x;
    if (t < 9*NK*CH) {                         // conv LUT (bias folded into tap 4)
        int co  = t & 31;
        int k   = (t >> 5) & 255;
        int tap = t >> 13;
        float s = (tap == 4) ? up1b[co] : 0.f;
#pragma unroll
        for (int ci = 0; ci < CH; ci++)
            s = fmaf(up1w[(co*CH + ci)*9 + tap], cb[k*CH + ci], s);
        ((float*)g_convlut)[(tap*NK + k)*CH + co] = s;
    } else if (t < 9*NK*CH + NK*CH) {          // mix LUT
        int u  = t - 9*NK*CH;
        int co = u & 31, k = u >> 5;
        float s = taub[co];
#pragma unroll
        for (int ci = 0; ci < CH; ci++)
            s = fmaf(tauw[co*CH + ci], cb[k*CH + ci], s);
        float beta = 1.f / (1.f + expf(-s));
        ((float*)g_Alut)[k*CH + co] = beta * cb[k*CH + co];
        ((float*)g_Blut)[k*CH + co] = 1.f - beta;
    } else if (t < 9*NK*CH + NK*CH + NK) {     // dec LUT
        int k = t - (9*NK*CH + NK*CH);
        float s = decb[0];
#pragma unroll
        for (int ci = 0; ci < CH; ci++)
            s = fmaf(decw[ci], cb[k*CH + ci], s);
        g_declut[k] = 1.f / (1.f + expf(-s));
    }
}

// ---------------- stem: conv3x3 (1->32) + relu ----------------
__global__ __launch_bounds__(256) void stem_kernel(
    const float* __restrict__ x, const float* __restrict__ w,
    const float* __restrict__ bias)
{
    __shared__ float sw[CH*9];
    __shared__ float sb[CH];
    if (threadIdx.x < CH*9) sw[threadIdx.x] = w[threadIdx.x];
    if (threadIdx.x < CH)   sb[threadIdx.x] = bias[threadIdx.x];
    __syncthreads();

    int p  = blockIdx.x * 256 + threadIdx.x;
    int xx = p & (WW-1);
    int yy = (p >> 8) & (HH-1);
    int b  = p >> 16;

    float v[9];
#pragma unroll
    for (int ky = 0; ky < 3; ky++)
#pragma unroll
        for (int kx = 0; kx < 3; kx++) {
            int iy = yy + ky - 1, ix = xx + kx - 1;
            v[ky*3+kx] = (iy >= 0 && iy < HH && ix >= 0 && ix < WW)
                         ? x[b*PLANE + iy*WW + ix] : 0.f;
        }

    float* ob = g_state + (size_t)b*CH*PLANE + yy*WW + xx;
#pragma unroll
    for (int co = 0; co < CH; co++) {
        float a = sb[co];
#pragma unroll
        for (int t = 0; t < 9; t++) a = fmaf(sw[co*9+t], v[t], a);
        ob[co*PLANE] = fmaxf(a, 0.f);
    }
}

// ---------------- dense conv3x3 (32->32)+relu, state->hidden (step 0 only) --
__global__ __launch_bounds__(256,2) void conv3x3_relu_kernel(
    const float* __restrict__ w, const float* __restrict__ bias)
{
    __shared__ float4 sw4[9*CH*CH/4];   // [tap][co][ci]
    __shared__ float  sb[CH];
    float* swf = (float*)sw4;
    for (int i = threadIdx.x; i < 9*CH*CH; i += 256) {
        int tap = i >> 10;
        int r   = i & 1023;
        int co  = r >> 5;
        int ci  = r & 31;
        swf[i] = w[(co*CH + ci)*9 + tap];
    }
    if (threadIdx.x < CH) sb[threadIdx.x] = bias[threadIdx.x];
    __syncthreads();

    int p  = blockIdx.x * 256 + threadIdx.x;
    int xx = p & (WW-1);
    int yy = (p >> 8) & (HH-1);
    int b  = p >> 16;
    const float* inb = g_state + (size_t)b*CH*PLANE;

    u64 acc2[CH];
#pragma unroll
    for (int co = 0; co < CH; co++) acc2[co] = 0ull;

    for (int ky = 0; ky < 3; ky++) {
        int iy = yy + ky - 1;
        if (iy < 0 || iy >= HH) continue;
        for (int kx = 0; kx < 3; kx++) {
            int ix = xx + kx - 1;
            if (ix < 0 || ix >= WW) continue;
            int tap = ky*3 + kx;
            const float* ip = inb + iy*WW + ix;
            u64 v2[CH/2];
#pragma unroll
            for (int q = 0; q < CH/2; q++)
                v2[q] = pk(ip[(2*q)*PLANE], ip[(2*q+1)*PLANE]);
            const ulonglong2* wt = (const ulonglong2*)(sw4 + tap*(CH*CH/4));
#pragma unroll
            for (int co = 0; co < CH; co++) {
                const ulonglong2* r = wt + co*8;
                u64 a = acc2[co];
#pragma unroll
                for (int j = 0; j < 8; j++) {
                    ulonglong2 c = r[j];
                    a = fma2(c.x, v2[2*j],   a);
                    a = fma2(c.y, v2[2*j+1], a);
                }
                acc2[co] = a;
            }
        }
    }

    float* ob = g_hidden + (size_t)b*CH*PLANE + yy*WW + xx;
#pragma unroll
    for (int co = 0; co < CH; co++) {
        float a, bq; upk(acc2[co], a, bq);
        ob[co*PLANE] = fmaxf(a + bq + sb[co], 0.f);
    }
}

// ---------------- dense fuse+VQ (step 0): state,hidden -> idxA --------------
__global__ __launch_bounds__(256,2) void fuse_dense_kernel(
    const float* __restrict__ up2w, const float* __restrict__ up2b,
    const float* __restrict__ tauw, const float* __restrict__ taub,
    const float* __restrict__ cb)
{
    __shared__ float4 s_cb4[NK*CH/4];   // 32 KB
    __shared__ float  s_cn[NK];
    __shared__ float4 s_u[CH*CH/4];
    __shared__ float4 s_t[CH*CH/4];
    __shared__ float  s_ub[CH], s_tb[CH];

    for (int i = threadIdx.x; i < NK*CH; i += 256) ((float*)s_cb4)[i] = cb[i];
    for (int i = threadIdx.x; i < CH*CH; i += 256) {
        ((float*)s_u)[i] = up2w[i];
        ((float*)s_t)[i] = tauw[i];
    }
    if (threadIdx.x < CH) { s_ub[threadIdx.x] = up2b[threadIdx.x];
                            s_tb[threadIdx.x] = taub[threadIdx.x]; }
    __syncthreads();
    {
        int k = threadIdx.x;
        const float* cf = (const float*)s_cb4;
        float s = 0.f;
#pragma unroll
        for (int ci = 0; ci < CH; ci++) s = fmaf(cf[k*CH+ci], cf[k*CH+ci], s);
        s_cn[k] = s;
    }
    __syncthreads();

    int p   = blockIdx.x * 256 + threadIdx.x;
    int b   = p >> 16;
    int off = p & (PLANE-1);
    const float* sp = g_state  + (size_t)b*CH*PLANE + off;
    const float* hp = g_hidden + (size_t)b*CH*PLANE + off;

    const ulonglong2* uw = (const ulonglong2*)s_u;
    const ulonglong2* tw = (const ulonglong2*)s_t;

    // phase 1: delta = up2 @ h + b  (h freed after)
    u64 d2[CH/2];
    {
        u64 h2[CH/2];
#pragma unroll
        for (int q = 0; q < CH/2; q++) h2[q] = pk(hp[(2*q)*PLANE], hp[(2*q+1)*PLANE]);
#pragma unroll
        for (int j = 0; j < CH/2; j++) {
            float d0 = gemv_row(uw + (2*j  )*8, h2) + s_ub[2*j  ];
            float d1 = gemv_row(uw + (2*j+1)*8, h2) + s_ub[2*j+1];
            d2[j] = pk(d0, d1);
        }
    }

    // phase 2: state pairs
    u64 s2[CH/2];
#pragma unroll
    for (int q = 0; q < CH/2; q++) s2[q] = pk(sp[(2*q)*PLANE], sp[(2*q+1)*PLANE]);

    // phase 3: beta + mix  (z overwrites d2; mul/mul/add like the reference)
#pragma unroll
    for (int j = 0; j < CH/2; j++) {
        float t0 = gemv_row(tw + (2*j  )*8, s2) + s_tb[2*j  ];
        float t1 = gemv_row(tw + (2*j+1)*8, s2) + s_tb[2*j+1];
        float b0 = 1.f / (1.f + expf(-t0));
        float b1 = 1.f / (1.f + expf(-t1));
        u64 bb = pk(b0, b1), ob = pk(1.f - b0, 1.f - b1);
        d2[j] = add2(mul2(bb, s2[j]), mul2(ob, d2[j]));
    }

    int k = vq_argmin(d2, (const ulonglong2*)s_cb4, s_cn);
    g_idxA[p] = (u8)k;
}

// ---------------- fast step (t>=1): idx -> idx ------------------------------
__global__ __launch_bounds__(256,2) void step_fast_kernel(
    const float* __restrict__ up2w, const float* __restrict__ up2b,
    const float* __restrict__ cb, int dir)
{
    __shared__ float4 s_cb4[NK*CH/4];
    __shared__ float  s_cn[NK];
    __shared__ float4 s_u[CH*CH/4];
    __shared__ float  s_ub[CH];

    for (int i = threadIdx.x; i < NK*CH; i += 256) ((float*)s_cb4)[i] = cb[i];
    for (int i = threadIdx.x; i < CH*CH; i += 256) ((float*)s_u)[i] = up2w[i];
    if (threadIdx.x < CH) s_ub[threadIdx.x] = up2b[threadIdx.x];
    __syncthreads();
    {
        int k = threadIdx.x;
        const float* cf = (const float*)s_cb4;
        float s = 0.f;
#pragma unroll
        for (int ci = 0; ci < CH; ci++) s = fmaf(cf[k*CH+ci], cf[k*CH+ci], s);
        s_cn[k] = s;
    }
    __syncthreads();

    const u8* iin  = dir ? g_idxB : g_idxA;
    u8*       iout = dir ? g_idxA : g_idxB;

    int p  = blockIdx.x * 256 + threadIdx.x;
    int xx = p & (WW-1);
    int yy = (p >> 8) & (HH-1);
    const u8* ib = iin + (p & ~(PLANE-1));
    int id0 = ib[yy*WW + xx];

    // hidden = relu(sum_taps T[tap][idx_nbr])  (up1 bias folded into tap 4)
    u64 h2[CH/2];
#pragma unroll
    for (int q = 0; q < CH/2; q++) h2[q] = 0ull;

    for (int ky = 0; ky < 3; ky++) {
        int iy = yy + ky - 1;
        if (iy < 0 || iy >= HH) continue;
        for (int kx = 0; kx < 3; kx++) {
            int ix = xx + kx - 1;
            if (ix < 0 || ix >= WW) continue;
            int id = ib[iy*WW + ix];
            const ulonglong2* row =
                (const ulonglong2*)(g_convlut + ((ky*3+kx)*NK + id)*(CH/4));
#pragma unroll
            for (int j = 0; j < 8; j++) {
                ulonglong2 c = row[j];
                h2[2*j]   = add2(h2[2*j],   c.x);
                h2[2*j+1] = add2(h2[2*j+1], c.y);
            }
        }
    }
#pragma unroll
    for (int q = 0; q < CH/2; q++) {
        float a, bq; upk(h2[q], a, bq);
        h2[q] = pk(fmaxf(a, 0.f), fmaxf(bq, 0.f));
    }

    // delta GEMV fused with mix: z = A[id0] + B[id0] * delta  (pairwise)
    const u64* ar = (const u64*)(g_Alut + id0*(CH/4));
    const u64* br = (const u64*)(g_Blut + id0*(CH/4));
    const ulonglong2* uw = (const ulonglong2*)s_u;
    u64 z2[CH/2];
#pragma unroll
    for (int j = 0; j < CH/2; j++) {
        float d0 = gemv_row(uw + (2*j  )*8, h2) + s_ub[2*j  ];
        float d1 = gemv_row(uw + (2*j+1)*8, h2) + s_ub[2*j+1];
        z2[j] = add2(ar[j], mul2(br[j], pk(d0, d1)));
    }

    int k = vq_argmin(z2, (const ulonglong2*)s_cb4, s_cn);
    iout[p] = (u8)k;
}

// ---------------- decoder: pure LUT ----------------
__global__ __launch_bounds__(256) void dec_lut_kernel(float* __restrict__ out)
{
    __shared__ float s_d[NK];
    s_d[threadIdx.x] = g_declut[threadIdx.x];
    __syncthreads();
    int p = blockIdx.x * 256 + threadIdx.x;
    out[p] = s_d[g_idxA[p]];
}

// ---------------------------------------------------------------------------
extern "C" void kernel_launch(void* const* d_in, const int* in_sizes, int n_in,
                              void* d_out, int out_size)
{
    const float* x      = (const float*)d_in[0];
    const float* stem_w = (const float*)d_in[1];
    const float* stem_b = (const float*)d_in[2];
    const float* up1_w  = (const float*)d_in[3];
    const float* up1_b  = (const float*)d_in[4];
    const float* up2_w  = (const float*)d_in[5];
    const float* up2_b  = (const float*)d_in[6];
    const float* tau_w  = (const float*)d_in[7];
    const float* tau_b  = (const float*)d_in[8];
    const float* cbk    = (const float*)d_in[9];
    const float* dec_w  = (const float*)d_in[10];
    const float* dec_b  = (const float*)d_in[11];
    // d_in[12] = n_steps (fixed at 5; loop is host-static for graph capture)

    dim3 grid(NPIX / 256), blk(256);

    stem_kernel<<<grid, blk>>>(x, stem_w, stem_b);
    build_luts<<<(9*NK*CH + NK*CH + NK + 255)/256, 256>>>(
        up1_w, up1_b, tau_w, tau_b, dec_w, dec_b, cbk);

    // step 0: dense path -> idxA
    conv3x3_relu_kernel<<<grid, blk>>>(up1_w, up1_b);
    fuse_dense_kernel<<<grid, blk>>>(up2_w, up2_b, tau_w, tau_b, cbk);

    // steps 1..4: LUT path, ping-pong A<->B (ends in A)
    step_fast_kernel<<<grid, blk>>>(up2_w, up2_b, cbk, 0); // A->B
    step_fast_kernel<<<grid, blk>>>(up2_w, up2_b, cbk, 1); // B->A
    step_fast_kernel<<<grid, blk>>>(up2_w, up2_b, cbk, 0); // A->B
    step_fast_kernel<<<grid, blk>>>(up2_w, up2_b, cbk, 1); // B->A

    dec_lut_kernel<<<grid, blk>>>((float*)d_out);
}